// round 3
// baseline (speedup 1.0000x reference)
#include <cuda_runtime.h>
#include <cuda_bf16.h>
#include <cstdint>
#include <math.h>

#define B_DIM 2
#define S_DIM 2048
#define D_DIM 2048
#define H_DIM 16
#define DH    128
#define M_DIM (B_DIM * S_DIM)   // 4096
#define K_DIM D_DIM             // 2048

// tcgen05 is arch-SPECIFIC: only legal when compiling for sm_103a/sm_100a etc.
// The harness also runs a plain compute_103 ptxas pass; give it an empty stub.
#if defined(__CUDA_ARCH_FEAT_SM103_ALL) || defined(__CUDA_ARCH_FEAT_SM100_ALL) || \
    defined(__CUDA_ARCH_SPECIFIC__) || defined(__CUDA_ARCH_FAMILY_SPECIFIC__)
#define HAS_TCGEN05 1
#else
#define HAS_TCGEN05 0
#endif

// ---------------- scratch (device globals: no allocation allowed) ----------
__device__ float g_Q [(size_t)B_DIM * H_DIM * S_DIM * DH];  // [B,H,S,dh]
__device__ float g_K [(size_t)B_DIM * H_DIM * S_DIM * DH];
__device__ float g_V [(size_t)B_DIM * H_DIM * S_DIM * DH];
__device__ float g_O [(size_t)B_DIM * H_DIM * S_DIM * DH];
__device__ float g_O2[(size_t)M_DIM * D_DIM];               // [B,S,D]

__device__ __nv_bfloat16 g_x_hi [(size_t)M_DIM * K_DIM];
__device__ __nv_bfloat16 g_x_lo [(size_t)M_DIM * K_DIM];
__device__ __nv_bfloat16 g_c_hi [(size_t)M_DIM * K_DIM];
__device__ __nv_bfloat16 g_c_lo [(size_t)M_DIM * K_DIM];
__device__ __nv_bfloat16 g_wq_hi[(size_t)D_DIM * K_DIM];
__device__ __nv_bfloat16 g_wq_lo[(size_t)D_DIM * K_DIM];
__device__ __nv_bfloat16 g_wk_hi[(size_t)D_DIM * K_DIM];
__device__ __nv_bfloat16 g_wk_lo[(size_t)D_DIM * K_DIM];
__device__ __nv_bfloat16 g_wv_hi[(size_t)D_DIM * K_DIM];
__device__ __nv_bfloat16 g_wv_lo[(size_t)D_DIM * K_DIM];
__device__ __nv_bfloat16 g_wo_hi[(size_t)D_DIM * K_DIM];
__device__ __nv_bfloat16 g_wo_lo[(size_t)D_DIM * K_DIM];

// ---------------- PTX helpers (guarded) -------------------------------------
#if HAS_TCGEN05

__device__ __forceinline__ uint32_t smem_u32(const void* p) {
    uint32_t a;
    asm("{ .reg .u64 t; cvta.to.shared.u64 t, %1; cvt.u32.u64 %0, t; }" : "=r"(a) : "l"(p));
    return a;
}
__device__ __forceinline__ uint32_t elect_one() {
    uint32_t pred;
    asm volatile("{\n.reg .pred p;\nelect.sync _|p, 0xFFFFFFFF;\nselp.b32 %0, 1, 0, p;\n}" : "=r"(pred));
    return pred;
}
#define TCGEN05_ALLOC(addr, n) \
    asm volatile("tcgen05.alloc.cta_group::1.sync.aligned.shared::cta.b32 [%0], %1;" \
                 :: "r"((uint32_t)(addr)), "r"((uint32_t)(n)) : "memory")
#define TCGEN05_DEALLOC(tm, n) \
    asm volatile("tcgen05.dealloc.cta_group::1.sync.aligned.b32 %0, %1;" :: "r"(tm), "r"((uint32_t)(n)))
#define TCGEN05_COMMIT(mbar) \
    asm volatile("tcgen05.commit.cta_group::1.mbarrier::arrive::one.shared::cluster.b64 [%0];" \
                 :: "r"((uint32_t)(mbar)) : "memory")
#define TCGEN05_FENCE_AFTER()  asm volatile("tcgen05.fence::after_thread_sync;" ::: "memory")
#define TCGEN05_WAIT_LD()      asm volatile("tcgen05.wait::ld.sync.aligned;" ::: "memory")
#define FENCE_PROXY_ASYNC()    asm volatile("fence.proxy.async.shared::cta;" ::: "memory")
#define MBARRIER_INIT(addr, cnt) \
    asm volatile("mbarrier.init.shared.b64 [%0], %1;" :: "r"((uint32_t)(addr)), "r"((uint32_t)(cnt)) : "memory")
#define MBARRIER_INVAL(addr) \
    asm volatile("mbarrier.inval.shared.b64 [%0];" :: "r"((uint32_t)(addr)) : "memory")
#define MBARRIER_WAIT_PARITY(mbar_addr, parity) do {                                   \
    uint32_t _mbar = (uint32_t)(mbar_addr);                                            \
    uint32_t _par  = (uint32_t)(parity);                                               \
    uint32_t _done;                                                                    \
    asm volatile("{\n.reg .pred p;\n"                                                  \
        "mbarrier.try_wait.parity.acquire.cta.shared::cta.b64 p, [%1], %2;\n"          \
        "selp.b32 %0, 1, 0, p;\n}" : "=r"(_done) : "r"(_mbar), "r"(_par) : "memory");  \
    if (!_done) {                                                                      \
        asm volatile("{\n.reg .pred P1;\n"                                             \
            "WL_%=:\n"                                                                 \
            "mbarrier.try_wait.parity.acquire.cta.shared::cta.b64 P1, [%0], %1, 0x989680;\n" \
            "@P1 bra.uni WD_%=;\n"                                                     \
            "bra.uni WL_%=;\n"                                                         \
            "WD_%=:\n}" :: "r"(_mbar), "r"(_par) : "memory");                          \
    }                                                                                  \
} while (0)

#define TCGEN05_LD_32X32B_X32(r, tmem_addr) \
    asm volatile( \
        "tcgen05.ld.sync.aligned.32x32b.x32.b32 " \
        "{%0, %1, %2, %3, %4, %5, %6, %7, " \
        " %8, %9, %10, %11, %12, %13, %14, %15, " \
        " %16, %17, %18, %19, %20, %21, %22, %23, " \
        " %24, %25, %26, %27, %28, %29, %30, %31}, [%32];" \
        : "=r"((r)[0]),  "=r"((r)[1]),  "=r"((r)[2]),  "=r"((r)[3]), \
          "=r"((r)[4]),  "=r"((r)[5]),  "=r"((r)[6]),  "=r"((r)[7]), \
          "=r"((r)[8]),  "=r"((r)[9]),  "=r"((r)[10]), "=r"((r)[11]), \
          "=r"((r)[12]), "=r"((r)[13]), "=r"((r)[14]), "=r"((r)[15]), \
          "=r"((r)[16]), "=r"((r)[17]), "=r"((r)[18]), "=r"((r)[19]), \
          "=r"((r)[20]), "=r"((r)[21]), "=r"((r)[22]), "=r"((r)[23]), \
          "=r"((r)[24]), "=r"((r)[25]), "=r"((r)[26]), "=r"((r)[27]), \
          "=r"((r)[28]), "=r"((r)[29]), "=r"((r)[30]), "=r"((r)[31]) \
        : "r"(tmem_addr))

// SW128 swizzle (Swizzle<3,4,3>)
#define SW128(off) ((off) ^ (((off) >> 3) & 0x70))

// SMEM descriptor: SW128, Blackwell v1, LBO=1 (16B), SBO=64 (1024B)
static __device__ __forceinline__ uint64_t make_desc(uint32_t addr) {
    const uint64_t base =
        (uint64_t(2) << 61) | (uint64_t(1) << 46) | (uint64_t(64) << 32) | (uint64_t(1) << 16);
    return base | ((uint64_t)(addr >> 4) & 0x3FFF);
}

__device__ __forceinline__ void mma_f16_ss(uint32_t d, uint64_t a, uint64_t b,
                                           uint32_t idesc, uint32_t en) {
    asm volatile(
        "{\n.reg .pred p;\n"
        "setp.ne.u32 p, %4, 0;\n"
        "tcgen05.mma.cta_group::1.kind::f16 [%0], %1, %2, %3, {%5, %5, %5, %5}, p;\n}"
        :: "r"(d), "l"(a), "l"(b), "r"(idesc), "r"(en), "r"(0u) : "memory");
}

// idesc kind::f16: F32 dtype, bf16 a/b, M=128, N=128
#define GEMM_IDESC ((1u << 4) | (1u << 7) | (1u << 10) | ((128u / 8) << 17) | ((128u / 16) << 24))

#endif  // HAS_TCGEN05

// ---------------- fp32 -> bf16 hi/lo split conversion -----------------------
__global__ __launch_bounds__(256) void convert_kernel(
    const float* __restrict__ src,
    __nv_bfloat16* __restrict__ hi,
    __nv_bfloat16* __restrict__ lo)
{
    size_t i = (size_t)blockIdx.x * 256 + threadIdx.x;   // float4 index
    float4 v = ((const float4*)src)[i];
    __nv_bfloat16 h0 = __float2bfloat16(v.x);
    __nv_bfloat16 h1 = __float2bfloat16(v.y);
    __nv_bfloat16 h2 = __float2bfloat16(v.z);
    __nv_bfloat16 h3 = __float2bfloat16(v.w);
    __nv_bfloat16 l0 = __float2bfloat16(v.x - __bfloat162float(h0));
    __nv_bfloat16 l1 = __float2bfloat16(v.y - __bfloat162float(h1));
    __nv_bfloat16 l2 = __float2bfloat16(v.z - __bfloat162float(h2));
    __nv_bfloat16 l3 = __float2bfloat16(v.w - __bfloat162float(h3));
    ((__nv_bfloat162*)hi)[2 * i + 0] = __nv_bfloat162(h0, h1);
    ((__nv_bfloat162*)hi)[2 * i + 1] = __nv_bfloat162(h2, h3);
    ((__nv_bfloat162*)lo)[2 * i + 0] = __nv_bfloat162(l0, l1);
    ((__nv_bfloat162*)lo)[2 * i + 1] = __nv_bfloat162(l2, l3);
}

// ---------------- tcgen05 split-bf16 GEMM: C = A @ W^T + bias ---------------
#define GK 64
#define SM_TMPTR 0
#define SM_MBAR  8
#define SM_AHI   1024
#define SM_ALO   (1024 + 16384)
#define SM_WHI   (1024 + 32768)
#define SM_WLO   (1024 + 49152)
#define SM_TOTAL (1024 + 65536)

template <int MODE>
__global__ __launch_bounds__(256) void gemm_tc_kernel(
    const __nv_bfloat16* __restrict__ Ahi,
    const __nv_bfloat16* __restrict__ Alo,
    const __nv_bfloat16* __restrict__ Whi,
    const __nv_bfloat16* __restrict__ Wlo,
    const float* __restrict__ bias,
    float* __restrict__ C)
{
#if HAS_TCGEN05
    extern __shared__ char smem[];
    const uint32_t sb = smem_u32(smem);
    const int tid = threadIdx.x;
    const int wid = tid >> 5;
    const int lid = tid & 31;
    const int bm = blockIdx.y * 128;
    const int bn = blockIdx.x * 128;

    if (wid == 4) TCGEN05_ALLOC(sb + SM_TMPTR, 128);
    if (tid == 0) MBARRIER_INIT(sb + SM_MBAR, 1);
    __syncthreads();
    uint32_t tmem;
    asm volatile("ld.shared.b32 %0, [%1];" : "=r"(tmem) : "r"(sb + SM_TMPTR));

    const uint64_t dAhi = make_desc(sb + SM_AHI);
    const uint64_t dAlo = make_desc(sb + SM_ALO);
    const uint64_t dWhi = make_desc(sb + SM_WHI);
    const uint64_t dWlo = make_desc(sb + SM_WLO);

    const int NCHUNK = K_DIM / GK;   // 32
    for (int c = 0; c < NCHUNK; ++c) {
        const int k0 = c * GK;
        const __nv_bfloat16* srcs[4] = { Ahi, Alo, Whi, Wlo };
        const int      rowb[4] = { bm, bm, bn, bn };
        const uint32_t dst[4]  = { sb + SM_AHI, sb + SM_ALO, sb + SM_WHI, sb + SM_WLO };
#pragma unroll
        for (int t = 0; t < 4; ++t) {
#pragma unroll
            for (int i = 0; i < 4; ++i) {
                int idx = tid + i * 256;        // 0..1023
                int r  = idx >> 3;
                int cc = idx & 7;               // 16B chunk within row
                float4 v = *(const float4*)(srcs[t] + (size_t)(rowb[t] + r) * K_DIM + k0 + cc * 8);
                uint32_t off = (uint32_t)(r * 128 + cc * 16);
                uint32_t sw = SW128(off);
                asm volatile("st.shared.v4.b32 [%0], {%1,%2,%3,%4};"
                             :: "r"(dst[t] + sw),
                                "r"(__float_as_uint(v.x)), "r"(__float_as_uint(v.y)),
                                "r"(__float_as_uint(v.z)), "r"(__float_as_uint(v.w))
                             : "memory");
            }
        }
        FENCE_PROXY_ASYNC();
        __syncthreads();

        if (wid == 4) {
            if (elect_one()) {
#pragma unroll
                for (int s = 0; s < 4; ++s) {       // 4 K16 steps per chunk
                    uint64_t offs = (uint64_t)(s * 2);
                    uint32_t en0 = (c == 0 && s == 0) ? 0u : 1u;
                    mma_f16_ss(tmem, dAhi + offs, dWhi + offs, GEMM_IDESC, en0);
                    mma_f16_ss(tmem, dAhi + offs, dWlo + offs, GEMM_IDESC, 1u);
                    mma_f16_ss(tmem, dAlo + offs, dWhi + offs, GEMM_IDESC, 1u);
                }
                TCGEN05_COMMIT(sb + SM_MBAR);
            }
        }
        MBARRIER_WAIT_PARITY(sb + SM_MBAR, c & 1);
    }
    TCGEN05_FENCE_AFTER();

    if (wid < 4) {
        const int m = bm + wid * 32 + lid;
        const int b = m / S_DIM;
        const int s = m - b * S_DIM;
#pragma unroll
        for (int part = 0; part < 4; ++part) {
            uint32_t r[32];
            TCGEN05_LD_32X32B_X32(r, tmem + part * 32);
            TCGEN05_WAIT_LD();
#pragma unroll
            for (int j = 0; j < 32; j += 4) {
                int n = bn + part * 32 + j;
                float4 o;
                o.x = __uint_as_float(r[j + 0]) + bias[n + 0];
                o.y = __uint_as_float(r[j + 1]) + bias[n + 1];
                o.z = __uint_as_float(r[j + 2]) + bias[n + 2];
                o.w = __uint_as_float(r[j + 3]) + bias[n + 3];
                if (MODE == 0) {
                    *(float4*)(C + (size_t)m * D_DIM + n) = o;
                } else {
                    int h  = n >> 7;
                    int dd = n & 127;
                    *(float4*)(C + (((size_t)(b * H_DIM + h) * S_DIM + s) * DH + dd)) = o;
                }
            }
        }
    }
    __syncthreads();
    if (tid == 0) MBARRIER_INVAL(sb + SM_MBAR);
    if (wid == 4) TCGEN05_DEALLOC(tmem, 128);
#endif  // HAS_TCGEN05
}

// ---------------- causal flash attention (fp32, 4 threads / row) ------------
#define BC 32

__global__ __launch_bounds__(512) void attn_kernel(
    const float* __restrict__ Q,
    const float* __restrict__ K,
    const float* __restrict__ V,
    float* __restrict__ O)
{
    __shared__ float Ks[BC][DH];
    __shared__ float Vs[BC][DH];

    const int bh = blockIdx.y;
    const int qt = gridDim.x - 1 - blockIdx.x;     // heavy tiles first
    const int tid = threadIdx.x;
    const int row = qt * 128 + (tid >> 2);
    const int d0 = (tid & 3) * 32;

    const float* Qb = Q + (size_t)bh * S_DIM * DH;
    const float* Kb = K + (size_t)bh * S_DIM * DH;
    const float* Vb = V + (size_t)bh * S_DIM * DH;
    float*       Ob = O + (size_t)bh * S_DIM * DH;

    const float scale = 0.08838834764831845f;      // 1/sqrt(128)

    float q[32];
#pragma unroll
    for (int u = 0; u < 32; u += 4) {
        float4 v = *(const float4*)(Qb + (size_t)row * DH + d0 + u);
        q[u + 0] = v.x * scale; q[u + 1] = v.y * scale;
        q[u + 2] = v.z * scale; q[u + 3] = v.w * scale;
    }

    float m = -1e30f, l = 0.f;
    float acc[32];
#pragma unroll
    for (int d = 0; d < 32; ++d) acc[d] = 0.f;

    const int nkt = qt * 4 + 4;
    for (int kt = 0; kt < nkt; ++kt) {
        const int kbase = kt * BC;
#pragma unroll
        for (int i = 0; i < 2; ++i) {
            int f = tid + i * 512;
            int r = f >> 5;
            int c = (f & 31) * 4;
            *(float4*)&Ks[r][c] = *(const float4*)(Kb + (size_t)(kbase + r) * DH + c);
            *(float4*)&Vs[r][c] = *(const float4*)(Vb + (size_t)(kbase + r) * DH + c);
        }
        __syncthreads();

        float sc[BC];
#pragma unroll
        for (int j = 0; j < BC; ++j) {
            float s = 0.f;
#pragma unroll
            for (int u = 0; u < 32; ++u)
                s += q[u] * Ks[j][d0 + u];
            s += __shfl_xor_sync(0xffffffffu, s, 1);
            s += __shfl_xor_sync(0xffffffffu, s, 2);
            sc[j] = s;
        }

        float mt = m;
#pragma unroll
        for (int j = 0; j < BC; ++j) {
            float v = (kbase + j <= row) ? sc[j] : -1e30f;
            mt = fmaxf(mt, v);
        }
        float corr = __expf(m - mt);
        m = mt;
        l *= corr;
#pragma unroll
        for (int d = 0; d < 32; ++d) acc[d] *= corr;

#pragma unroll
        for (int j = 0; j < BC; ++j) {
            sc[j] = (kbase + j <= row) ? __expf(sc[j] - mt) : 0.f;
            l += sc[j];
        }
#pragma unroll
        for (int j = 0; j < BC; ++j) {
#pragma unroll
            for (int d = 0; d < 32; ++d)
                acc[d] += sc[j] * Vs[j][d0 + d];
        }
        __syncthreads();
    }

    const float inv = 1.f / l;
#pragma unroll
    for (int d = 0; d < 32; d += 4) {
        float4 o;
        o.x = acc[d + 0] * inv; o.y = acc[d + 1] * inv;
        o.z = acc[d + 2] * inv; o.w = acc[d + 3] * inv;
        *(float4*)(Ob + (size_t)row * DH + d0 + d) = o;
    }
}

// ---------------- [B,H,S,dh] -> [B,S,D] transpose --------------------------
__global__ __launch_bounds__(256) void transpose_kernel(
    const float* __restrict__ O, float* __restrict__ O2)
{
    size_t idx = (size_t)blockIdx.x * blockDim.x + threadIdx.x;  // float4 id
    int d4 = (int)(idx & 31);
    int s  = (int)((idx >> 5) & 2047);
    int h  = (int)((idx >> 16) & 15);
    int b  = (int)(idx >> 20);
    float4 v = ((const float4*)O)[idx];
    ((float4*)O2)[((size_t)(b * S_DIM + s)) * (D_DIM / 4) + h * 32 + d4] = v;
}

// ---------------- launch ----------------------------------------------------
extern "C" void kernel_launch(void* const* d_in, const int* in_sizes, int n_in,
                              void* d_out, int out_size)
{
    const float* x  = (const float*)d_in[0];
    const float* Wq = (const float*)d_in[1];
    const float* bq = (const float*)d_in[2];
    const float* Wk = (const float*)d_in[3];
    const float* bk = (const float*)d_in[4];
    const float* Wv = (const float*)d_in[5];
    const float* bv = (const float*)d_in[6];
    const float* Wo = (const float*)d_in[7];
    const float* bo = (const float*)d_in[8];
    float* out = (float*)d_out;

    float *qp, *kp, *vp, *op, *o2p;
    cudaGetSymbolAddress((void**)&qp,  g_Q);
    cudaGetSymbolAddress((void**)&kp,  g_K);
    cudaGetSymbolAddress((void**)&vp,  g_V);
    cudaGetSymbolAddress((void**)&op,  g_O);
    cudaGetSymbolAddress((void**)&o2p, g_O2);

    __nv_bfloat16 *xh, *xl, *ch, *cl;
    __nv_bfloat16 *wqh, *wql, *wkh, *wkl, *wvh, *wvl, *woh, *wol;
    cudaGetSymbolAddress((void**)&xh,  g_x_hi);  cudaGetSymbolAddress((void**)&xl,  g_x_lo);
    cudaGetSymbolAddress((void**)&ch,  g_c_hi);  cudaGetSymbolAddress((void**)&cl,  g_c_lo);
    cudaGetSymbolAddress((void**)&wqh, g_wq_hi); cudaGetSymbolAddress((void**)&wql, g_wq_lo);
    cudaGetSymbolAddress((void**)&wkh, g_wk_hi); cudaGetSymbolAddress((void**)&wkl, g_wk_lo);
    cudaGetSymbolAddress((void**)&wvh, g_wv_hi); cudaGetSymbolAddress((void**)&wvl, g_wv_lo);
    cudaGetSymbolAddress((void**)&woh, g_wo_hi); cudaGetSymbolAddress((void**)&wol, g_wo_lo);

    cudaFuncSetAttribute(gemm_tc_kernel<0>, cudaFuncAttributeMaxDynamicSharedMemorySize, SM_TOTAL);
    cudaFuncSetAttribute(gemm_tc_kernel<1>, cudaFuncAttributeMaxDynamicSharedMemorySize, SM_TOTAL);

    const int NX4 = (M_DIM * D_DIM) / 4;
    const int NW4 = (D_DIM * D_DIM) / 4;

    convert_kernel<<<NX4 / 256, 256>>>(x,  xh,  xl);
    convert_kernel<<<NW4 / 256, 256>>>(Wq, wqh, wql);
    convert_kernel<<<NW4 / 256, 256>>>(Wk, wkh, wkl);
    convert_kernel<<<NW4 / 256, 256>>>(Wv, wvh, wvl);
    convert_kernel<<<NW4 / 256, 256>>>(Wo, woh, wol);

    dim3 gg(D_DIM / 128, M_DIM / 128);     // (16, 32)
    gemm_tc_kernel<1><<<gg, 256, SM_TOTAL>>>(xh, xl, wqh, wql, bq, qp);
    gemm_tc_kernel<1><<<gg, 256, SM_TOTAL>>>(xh, xl, wkh, wkl, bk, kp);
    gemm_tc_kernel<1><<<gg, 256, SM_TOTAL>>>(xh, xl, wvh, wvl, bv, vp);

    dim3 ga(S_DIM / 128, B_DIM * H_DIM);   // (16, 32)
    attn_kernel<<<ga, 512>>>(qp, kp, vp, op);

    transpose_kernel<<<(B_DIM * H_DIM * S_DIM * DH / 4) / 256, 256>>>(op, o2p);

    convert_kernel<<<NX4 / 256, 256>>>(o2p, ch, cl);

    gemm_tc_kernel<0><<<gg, 256, SM_TOTAL>>>(ch, cl, woh, wol, bo, out);
}

// round 4
// speedup vs baseline: 1.7550x; 1.7550x over previous
#include <cuda_runtime.h>
#include <cuda_bf16.h>
#include <cstdint>
#include <math.h>

#define B_DIM 2
#define S_DIM 2048
#define D_DIM 2048
#define H_DIM 16
#define DH    128
#define M_DIM (B_DIM * S_DIM)   // 4096
#define K_DIM D_DIM             // 2048

#define GK      64              // K-chunk (64 bf16 = 128B rows, SW128 atom)
#define NCHUNK  (K_DIM / GK)    // 32
#define A_CHUNK_BYTES ((uint32_t)M_DIM * 128u)   // 524288
#define W_CHUNK_BYTES ((uint32_t)D_DIM * 128u)   // 262144

// tcgen05 / bulk-async are arch-SPECIFIC: the harness also runs a plain
// compute_103 ptxas pass; give that pass an empty stub.
#if defined(__CUDA_ARCH_FEAT_SM103_ALL) || defined(__CUDA_ARCH_FEAT_SM100_ALL) || \
    defined(__CUDA_ARCH_SPECIFIC__) || defined(__CUDA_ARCH_FAMILY_SPECIFIC__)
#define HAS_TCGEN05 1
#else
#define HAS_TCGEN05 0
#endif

// ---------------- scratch (device globals: no allocation allowed) ----------
__device__ float g_Q [(size_t)B_DIM * H_DIM * S_DIM * DH];  // [B,H,S,dh]
__device__ float g_K [(size_t)B_DIM * H_DIM * S_DIM * DH];
__device__ float g_V [(size_t)B_DIM * H_DIM * S_DIM * DH];
__device__ float g_O [(size_t)B_DIM * H_DIM * S_DIM * DH];
__device__ float g_O2[(size_t)M_DIM * D_DIM];               // [B,S,D]

// pre-swizzled chunk-major bf16 hi/lo buffers (byte-addressed)
__device__ uint8_t g_x_hi [(size_t)M_DIM * K_DIM * 2];
__device__ uint8_t g_x_lo [(size_t)M_DIM * K_DIM * 2];
__device__ uint8_t g_c_hi [(size_t)M_DIM * K_DIM * 2];
__device__ uint8_t g_c_lo [(size_t)M_DIM * K_DIM * 2];
__device__ uint8_t g_wq_hi[(size_t)D_DIM * K_DIM * 2];
__device__ uint8_t g_wq_lo[(size_t)D_DIM * K_DIM * 2];
__device__ uint8_t g_wk_hi[(size_t)D_DIM * K_DIM * 2];
__device__ uint8_t g_wk_lo[(size_t)D_DIM * K_DIM * 2];
__device__ uint8_t g_wv_hi[(size_t)D_DIM * K_DIM * 2];
__device__ uint8_t g_wv_lo[(size_t)D_DIM * K_DIM * 2];
__device__ uint8_t g_wo_hi[(size_t)D_DIM * K_DIM * 2];
__device__ uint8_t g_wo_lo[(size_t)D_DIM * K_DIM * 2];

// SW128 swizzle (Swizzle<3,4,3>) on byte offsets
#define SW128(off) ((off) ^ (((off) >> 3) & 0x70))

// ---------------- PTX helpers (guarded) -------------------------------------
#if HAS_TCGEN05

__device__ __forceinline__ uint32_t smem_u32(const void* p) {
    uint32_t a;
    asm("{ .reg .u64 t; cvta.to.shared.u64 t, %1; cvt.u32.u64 %0, t; }" : "=r"(a) : "l"(p));
    return a;
}
__device__ __forceinline__ uint32_t elect_one() {
    uint32_t pred;
    asm volatile("{\n.reg .pred p;\nelect.sync _|p, 0xFFFFFFFF;\nselp.b32 %0, 1, 0, p;\n}" : "=r"(pred));
    return pred;
}
#define TCGEN05_ALLOC(addr, n) \
    asm volatile("tcgen05.alloc.cta_group::1.sync.aligned.shared::cta.b32 [%0], %1;" \
                 :: "r"((uint32_t)(addr)), "r"((uint32_t)(n)) : "memory")
#define TCGEN05_DEALLOC(tm, n) \
    asm volatile("tcgen05.dealloc.cta_group::1.sync.aligned.b32 %0, %1;" :: "r"(tm), "r"((uint32_t)(n)))
#define TCGEN05_COMMIT(mbar) \
    asm volatile("tcgen05.commit.cta_group::1.mbarrier::arrive::one.shared::cluster.b64 [%0];" \
                 :: "r"((uint32_t)(mbar)) : "memory")
#define TCGEN05_FENCE_AFTER()  asm volatile("tcgen05.fence::after_thread_sync;" ::: "memory")
#define TCGEN05_WAIT_LD()      asm volatile("tcgen05.wait::ld.sync.aligned;" ::: "memory")
#define MBARRIER_INIT(addr, cnt) \
    asm volatile("mbarrier.init.shared.b64 [%0], %1;" :: "r"((uint32_t)(addr)), "r"((uint32_t)(cnt)) : "memory")
#define MBARRIER_INVAL(addr) \
    asm volatile("mbarrier.inval.shared.b64 [%0];" :: "r"((uint32_t)(addr)) : "memory")
#define MBARRIER_EXPECT_TX(addr, bytes) \
    asm volatile("mbarrier.arrive.expect_tx.shared.b64 _, [%0], %1;" \
                 :: "r"((uint32_t)(addr)), "r"((uint32_t)(bytes)) : "memory")
#define MBARRIER_WAIT_PARITY(mbar_addr, parity) do {                                   \
    uint32_t _mbar = (uint32_t)(mbar_addr);                                            \
    uint32_t _par  = (uint32_t)(parity);                                               \
    uint32_t _done;                                                                    \
    asm volatile("{\n.reg .pred p;\n"                                                  \
        "mbarrier.try_wait.parity.acquire.cta.shared::cta.b64 p, [%1], %2;\n"          \
        "selp.b32 %0, 1, 0, p;\n}" : "=r"(_done) : "r"(_mbar), "r"(_par) : "memory");  \
    if (!_done) {                                                                      \
        asm volatile("{\n.reg .pred P1;\n"                                             \
            "WL_%=:\n"                                                                 \
            "mbarrier.try_wait.parity.acquire.cta.shared::cta.b64 P1, [%0], %1, 0x989680;\n" \
            "@P1 bra.uni WD_%=;\n"                                                     \
            "bra.uni WL_%=;\n"                                                         \
            "WD_%=:\n}" :: "r"(_mbar), "r"(_par) : "memory");                          \
    }                                                                                  \
} while (0)

// bulk async copy gmem -> smem (UBLKCP), completion via mbarrier tx-count
#define BULK_G2S(dst, src, bytes, mbar) \
    asm volatile("cp.async.bulk.shared::cta.global.mbarrier::complete_tx::bytes [%0], [%1], %2, [%3];" \
                 :: "r"((uint32_t)(dst)), "l"(src), "r"((uint32_t)(bytes)), "r"((uint32_t)(mbar)) : "memory")

#define TCGEN05_LD_32X32B_X32(r, tmem_addr) \
    asm volatile( \
        "tcgen05.ld.sync.aligned.32x32b.x32.b32 " \
        "{%0, %1, %2, %3, %4, %5, %6, %7, " \
        " %8, %9, %10, %11, %12, %13, %14, %15, " \
        " %16, %17, %18, %19, %20, %21, %22, %23, " \
        " %24, %25, %26, %27, %28, %29, %30, %31}, [%32];" \
        : "=r"((r)[0]),  "=r"((r)[1]),  "=r"((r)[2]),  "=r"((r)[3]), \
          "=r"((r)[4]),  "=r"((r)[5]),  "=r"((r)[6]),  "=r"((r)[7]), \
          "=r"((r)[8]),  "=r"((r)[9]),  "=r"((r)[10]), "=r"((r)[11]), \
          "=r"((r)[12]), "=r"((r)[13]), "=r"((r)[14]), "=r"((r)[15]), \
          "=r"((r)[16]), "=r"((r)[17]), "=r"((r)[18]), "=r"((r)[19]), \
          "=r"((r)[20]), "=r"((r)[21]), "=r"((r)[22]), "=r"((r)[23]), \
          "=r"((r)[24]), "=r"((r)[25]), "=r"((r)[26]), "=r"((r)[27]), \
          "=r"((r)[28]), "=r"((r)[29]), "=r"((r)[30]), "=r"((r)[31]) \
        : "r"(tmem_addr))

// SMEM descriptor: SW128, Blackwell v1, LBO=1 (16B), SBO=64 (1024B)
static __device__ __forceinline__ uint64_t make_desc(uint32_t addr) {
    const uint64_t base =
        (uint64_t(2) << 61) | (uint64_t(1) << 46) | (uint64_t(64) << 32) | (uint64_t(1) << 16);
    return base | ((uint64_t)(addr >> 4) & 0x3FFF);
}

__device__ __forceinline__ void mma_f16_ss(uint32_t d, uint64_t a, uint64_t b,
                                           uint32_t idesc, uint32_t en) {
    asm volatile(
        "{\n.reg .pred p;\n"
        "setp.ne.u32 p, %4, 0;\n"
        "tcgen05.mma.cta_group::1.kind::f16 [%0], %1, %2, %3, {%5, %5, %5, %5}, p;\n}"
        :: "r"(d), "l"(a), "l"(b), "r"(idesc), "r"(en), "r"(0u) : "memory");
}

// idesc kind::f16: F32 dtype, bf16 a/b, M=128, N=128
#define GEMM_IDESC ((1u << 4) | (1u << 7) | (1u << 10) | ((128u / 8) << 17) | ((128u / 16) << 24))

#endif  // HAS_TCGEN05

// ---------------- fp32 -> pre-swizzled chunk-major bf16 hi/lo ---------------
// Output byte layout: chunk*(R*128) + (m/8)*1024 + SW128((m%8)*128 + ((k%64)/8)*16)
__device__ __forceinline__ uint32_t pack_bf2(float a, float b) {
    __nv_bfloat162 t(__float2bfloat16(a), __float2bfloat16(b));
    return *(uint32_t*)&t;
}
__global__ __launch_bounds__(256) void convert_sw_kernel(
    const float* __restrict__ src,
    uint8_t* __restrict__ hi,
    uint8_t* __restrict__ lo,
    int R)
{
    int idx = blockIdx.x * 256 + threadIdx.x;
    int k = (idx & 255) * 8;          // 0..2040
    int m = idx >> 8;
    const float* p = src + (size_t)m * K_DIM + k;
    float4 v0 = *(const float4*)p;
    float4 v1 = *(const float4*)(p + 4);

    float h[8] = { v0.x, v0.y, v0.z, v0.w, v1.x, v1.y, v1.z, v1.w };
    float r[8];
#pragma unroll
    for (int i = 0; i < 8; ++i) {
        float hv = __bfloat162float(__float2bfloat16(h[i]));
        r[i] = h[i] - hv;
    }
    uint4 uh, ul;
    uh.x = pack_bf2(h[0], h[1]); uh.y = pack_bf2(h[2], h[3]);
    uh.z = pack_bf2(h[4], h[5]); uh.w = pack_bf2(h[6], h[7]);
    ul.x = pack_bf2(r[0], r[1]); ul.y = pack_bf2(r[2], r[3]);
    ul.z = pack_bf2(r[4], r[5]); ul.w = pack_bf2(r[6], r[7]);

    uint32_t inblk = (uint32_t)((m & 7) * 128 + ((k >> 3) & 7) * 16);
    uint32_t off = (uint32_t)(k >> 6) * (uint32_t)(R * 128)
                 + (uint32_t)(m >> 3) * 1024u + SW128(inblk);
    *(uint4*)(hi + off) = uh;
    *(uint4*)(lo + off) = ul;
}

// ---------------- pipelined tcgen05 split-bf16 GEMM: C = A @ W^T + bias -----
// 3-stage producer/consumer: cp.async.bulk loads chunk tiles (pre-swizzled),
// MMA-elect issues 12 MMAs/chunk, commit recycles the stage buffer.
#define SM_TM       0
#define SM_DONE     8
#define SM_FULL(s)  (16 + 8 * (s))
#define SM_EMPTY(s) (48 + 8 * (s))
#define SM_STAGE(s) (1024 + 65536 * (s))
#define SM_TOTAL    (1024 + 3 * 65536)   // 197632

template <int MODE>
__global__ __launch_bounds__(256) void gemm_tc_kernel(
    const uint8_t* __restrict__ Ahi,
    const uint8_t* __restrict__ Alo,
    const uint8_t* __restrict__ Whi,
    const uint8_t* __restrict__ Wlo,
    const float* __restrict__ bias,
    float* __restrict__ C)
{
#if HAS_TCGEN05
    extern __shared__ char smem[];
    const uint32_t sb = smem_u32(smem);
    const int tid = threadIdx.x;
    const int wid = tid >> 5;
    const int lid = tid & 31;
    const int bm = blockIdx.y * 128;
    const int bn = blockIdx.x * 128;

    if (wid == 4) TCGEN05_ALLOC(sb + SM_TM, 128);
    if (tid == 0) {
        MBARRIER_INIT(sb + SM_DONE, 1);
#pragma unroll
        for (int s = 0; s < 3; ++s) {
            MBARRIER_INIT(sb + SM_FULL(s), 1);
            MBARRIER_INIT(sb + SM_EMPTY(s), 1);
        }
    }
    __syncthreads();
    uint32_t tmem;
    asm volatile("ld.shared.b32 %0, [%1];" : "=r"(tmem) : "r"(sb + SM_TM));

    if (tid == 0) {
        // -------- producer: one bulk copy per tile per chunk --------
        const uint8_t* a_hi = Ahi + (uint32_t)bm * 128u;
        const uint8_t* a_lo = Alo + (uint32_t)bm * 128u;
        const uint8_t* w_hi = Whi + (uint32_t)bn * 128u;
        const uint8_t* w_lo = Wlo + (uint32_t)bn * 128u;
        int s = 0, ph = 1;
        for (int c = 0; c < NCHUNK; ++c) {
            MBARRIER_WAIT_PARITY(sb + SM_EMPTY(s), ph);
            uint32_t full = sb + SM_FULL(s);
            uint32_t stg  = sb + SM_STAGE(s);
            MBARRIER_EXPECT_TX(full, 65536);
            BULK_G2S(stg +     0, a_hi + (uint32_t)c * A_CHUNK_BYTES, 16384, full);
            BULK_G2S(stg + 16384, a_lo + (uint32_t)c * A_CHUNK_BYTES, 16384, full);
            BULK_G2S(stg + 32768, w_hi + (uint32_t)c * W_CHUNK_BYTES, 16384, full);
            BULK_G2S(stg + 49152, w_lo + (uint32_t)c * W_CHUNK_BYTES, 16384, full);
            if (++s == 3) { s = 0; ph ^= 1; }
        }
    } else if (wid == 4 && elect_one()) {
        // -------- consumer: MMA issue; commit recycles stage --------
        int s = 0, ph = 0;
        for (int c = 0; c < NCHUNK; ++c) {
            MBARRIER_WAIT_PARITY(sb + SM_FULL(s), ph);
            uint32_t stg = sb + SM_STAGE(s);
            uint64_t dAhi = make_desc(stg);
            uint64_t dAlo = make_desc(stg + 16384);
            uint64_t dWhi = make_desc(stg + 32768);
            uint64_t dWlo = make_desc(stg + 49152);
#pragma unroll
            for (int st = 0; st < 4; ++st) {            // 4 K16 steps
                uint64_t o = (uint64_t)(st * 2);
                mma_f16_ss(tmem, dAhi + o, dWhi + o, GEMM_IDESC, (c > 0 || st > 0) ? 1u : 0u);
                mma_f16_ss(tmem, dAhi + o, dWlo + o, GEMM_IDESC, 1u);
                mma_f16_ss(tmem, dAlo + o, dWhi + o, GEMM_IDESC, 1u);
            }
            TCGEN05_COMMIT(sb + SM_EMPTY(s));
            if (++s == 3) { s = 0; ph ^= 1; }
        }
        TCGEN05_COMMIT(sb + SM_DONE);
    }

    // -------- everyone: wait for all MMAs, then epilogue --------
    MBARRIER_WAIT_PARITY(sb + SM_DONE, 0);
    TCGEN05_FENCE_AFTER();

    if (wid < 4) {
        const int m = bm + wid * 32 + lid;
        const int b = m / S_DIM;
        const int s = m - b * S_DIM;
#pragma unroll
        for (int part = 0; part < 4; ++part) {
            uint32_t r[32];
            TCGEN05_LD_32X32B_X32(r, tmem + part * 32);
            TCGEN05_WAIT_LD();
#pragma unroll
            for (int j = 0; j < 32; j += 4) {
                int n = bn + part * 32 + j;
                float4 o;
                o.x = __uint_as_float(r[j + 0]) + bias[n + 0];
                o.y = __uint_as_float(r[j + 1]) + bias[n + 1];
                o.z = __uint_as_float(r[j + 2]) + bias[n + 2];
                o.w = __uint_as_float(r[j + 3]) + bias[n + 3];
                if (MODE == 0) {
                    *(float4*)(C + (size_t)m * D_DIM + n) = o;
                } else {
                    int h  = n >> 7;
                    int dd = n & 127;
                    *(float4*)(C + (((size_t)(b * H_DIM + h) * S_DIM + s) * DH + dd)) = o;
                }
            }
        }
    }
    __syncthreads();
    if (tid == 0) {
        MBARRIER_INVAL(sb + SM_DONE);
#pragma unroll
        for (int s = 0; s < 3; ++s) {
            MBARRIER_INVAL(sb + SM_FULL(s));
            MBARRIER_INVAL(sb + SM_EMPTY(s));
        }
    }
    __syncthreads();
    if (wid == 4) TCGEN05_DEALLOC(tmem, 128);
#endif  // HAS_TCGEN05
}

// ---------------- causal flash attention (fp32, 4 threads / row) ------------
#define BC 32

__global__ __launch_bounds__(512) void attn_kernel(
    const float* __restrict__ Q,
    const float* __restrict__ K,
    const float* __restrict__ V,
    float* __restrict__ O)
{
    __shared__ float Ks[BC][DH];
    __shared__ float Vs[BC][DH];

    const int bh = blockIdx.y;
    const int qt = gridDim.x - 1 - blockIdx.x;     // heavy tiles first
    const int tid = threadIdx.x;
    const int row = qt * 128 + (tid >> 2);
    const int d0 = (tid & 3) * 32;

    const float* Qb = Q + (size_t)bh * S_DIM * DH;
    const float* Kb = K + (size_t)bh * S_DIM * DH;
    const float* Vb = V + (size_t)bh * S_DIM * DH;
    float*       Ob = O + (size_t)bh * S_DIM * DH;

    const float scale = 0.08838834764831845f;      // 1/sqrt(128)

    float q[32];
#pragma unroll
    for (int u = 0; u < 32; u += 4) {
        float4 v = *(const float4*)(Qb + (size_t)row * DH + d0 + u);
        q[u + 0] = v.x * scale; q[u + 1] = v.y * scale;
        q[u + 2] = v.z * scale; q[u + 3] = v.w * scale;
    }

    float m = -1e30f, l = 0.f;
    float acc[32];
#pragma unroll
    for (int d = 0; d < 32; ++d) acc[d] = 0.f;

    const int nkt = qt * 4 + 4;
    for (int kt = 0; kt < nkt; ++kt) {
        const int kbase = kt * BC;
#pragma unroll
        for (int i = 0; i < 2; ++i) {
            int f = tid + i * 512;
            int r = f >> 5;
            int c = (f & 31) * 4;
            *(float4*)&Ks[r][c] = *(const float4*)(Kb + (size_t)(kbase + r) * DH + c);
            *(float4*)&Vs[r][c] = *(const float4*)(Vb + (size_t)(kbase + r) * DH + c);
        }
        __syncthreads();

        float sc[BC];
#pragma unroll
        for (int j = 0; j < BC; ++j) {
            float s = 0.f;
#pragma unroll
            for (int u = 0; u < 32; ++u)
                s += q[u] * Ks[j][d0 + u];
            s += __shfl_xor_sync(0xffffffffu, s, 1);
            s += __shfl_xor_sync(0xffffffffu, s, 2);
            sc[j] = s;
        }

        float mt = m;
#pragma unroll
        for (int j = 0; j < BC; ++j) {
            float v = (kbase + j <= row) ? sc[j] : -1e30f;
            mt = fmaxf(mt, v);
        }
        float corr = __expf(m - mt);
        m = mt;
        l *= corr;
#pragma unroll
        for (int d = 0; d < 32; ++d) acc[d] *= corr;

#pragma unroll
        for (int j = 0; j < BC; ++j) {
            sc[j] = (kbase + j <= row) ? __expf(sc[j] - mt) : 0.f;
            l += sc[j];
        }
#pragma unroll
        for (int j = 0; j < BC; ++j) {
#pragma unroll
            for (int d = 0; d < 32; ++d)
                acc[d] += sc[j] * Vs[j][d0 + d];
        }
        __syncthreads();
    }

    const float inv = 1.f / l;
#pragma unroll
    for (int d = 0; d < 32; d += 4) {
        float4 o;
        o.x = acc[d + 0] * inv; o.y = acc[d + 1] * inv;
        o.z = acc[d + 2] * inv; o.w = acc[d + 3] * inv;
        *(float4*)(Ob + (size_t)row * DH + d0 + d) = o;
    }
}

// ---------------- [B,H,S,dh] -> [B,S,D] transpose --------------------------
__global__ __launch_bounds__(256) void transpose_kernel(
    const float* __restrict__ O, float* __restrict__ O2)
{
    size_t idx = (size_t)blockIdx.x * blockDim.x + threadIdx.x;  // float4 id
    int d4 = (int)(idx & 31);
    int s  = (int)((idx >> 5) & 2047);
    int h  = (int)((idx >> 16) & 15);
    int b  = (int)(idx >> 20);
    float4 v = ((const float4*)O)[idx];
    ((float4*)O2)[((size_t)(b * S_DIM + s)) * (D_DIM / 4) + h * 32 + d4] = v;
}

// ---------------- launch ----------------------------------------------------
extern "C" void kernel_launch(void* const* d_in, const int* in_sizes, int n_in,
                              void* d_out, int out_size)
{
    const float* x  = (const float*)d_in[0];
    const float* Wq = (const float*)d_in[1];
    const float* bq = (const float*)d_in[2];
    const float* Wk = (const float*)d_in[3];
    const float* bk = (const float*)d_in[4];
    const float* Wv = (const float*)d_in[5];
    const float* bv = (const float*)d_in[6];
    const float* Wo = (const float*)d_in[7];
    const float* bo = (const float*)d_in[8];
    float* out = (float*)d_out;

    float *qp, *kp, *vp, *op, *o2p;
    cudaGetSymbolAddress((void**)&qp,  g_Q);
    cudaGetSymbolAddress((void**)&kp,  g_K);
    cudaGetSymbolAddress((void**)&vp,  g_V);
    cudaGetSymbolAddress((void**)&op,  g_O);
    cudaGetSymbolAddress((void**)&o2p, g_O2);

    uint8_t *xh, *xl, *ch, *cl;
    uint8_t *wqh, *wql, *wkh, *wkl, *wvh, *wvl, *woh, *wol;
    cudaGetSymbolAddress((void**)&xh,  g_x_hi);  cudaGetSymbolAddress((void**)&xl,  g_x_lo);
    cudaGetSymbolAddress((void**)&ch,  g_c_hi);  cudaGetSymbolAddress((void**)&cl,  g_c_lo);
    cudaGetSymbolAddress((void**)&wqh, g_wq_hi); cudaGetSymbolAddress((void**)&wql, g_wq_lo);
    cudaGetSymbolAddress((void**)&wkh, g_wk_hi); cudaGetSymbolAddress((void**)&wkl, g_wk_lo);
    cudaGetSymbolAddress((void**)&wvh, g_wv_hi); cudaGetSymbolAddress((void**)&wvl, g_wv_lo);
    cudaGetSymbolAddress((void**)&woh, g_wo_hi); cudaGetSymbolAddress((void**)&wol, g_wo_lo);

    cudaFuncSetAttribute(gemm_tc_kernel<0>, cudaFuncAttributeMaxDynamicSharedMemorySize, SM_TOTAL);
    cudaFuncSetAttribute(gemm_tc_kernel<1>, cudaFuncAttributeMaxDynamicSharedMemorySize, SM_TOTAL);

    const int GBX = (M_DIM * K_DIM / 8) / 256;   // activation convert blocks
    const int GBW = (D_DIM * K_DIM / 8) / 256;   // weight convert blocks

    convert_sw_kernel<<<GBX, 256>>>(x,  xh,  xl,  M_DIM);
    convert_sw_kernel<<<GBW, 256>>>(Wq, wqh, wql, D_DIM);
    convert_sw_kernel<<<GBW, 256>>>(Wk, wkh, wkl, D_DIM);
    convert_sw_kernel<<<GBW, 256>>>(Wv, wvh, wvl, D_DIM);
    convert_sw_kernel<<<GBW, 256>>>(Wo, woh, wol, D_DIM);

    dim3 gg(D_DIM / 128, M_DIM / 128);     // (16, 32)
    gemm_tc_kernel<1><<<gg, 256, SM_TOTAL>>>(xh, xl, wqh, wql, bq, qp);
    gemm_tc_kernel<1><<<gg, 256, SM_TOTAL>>>(xh, xl, wkh, wkl, bk, kp);
    gemm_tc_kernel<1><<<gg, 256, SM_TOTAL>>>(xh, xl, wvh, wvl, bv, vp);

    dim3 ga(S_DIM / 128, B_DIM * H_DIM);   // (16, 32)
    attn_kernel<<<ga, 512>>>(qp, kp, vp, op);

    transpose_kernel<<<(B_DIM * H_DIM * S_DIM * DH / 4) / 256, 256>>>(op, o2p);

    convert_sw_kernel<<<GBX, 256>>>(o2p, ch, cl, M_DIM);

    gemm_tc_kernel<0><<<gg, 256, SM_TOTAL>>>(ch, cl, woh, wol, bo, out);
}